// round 1
// baseline (speedup 1.0000x reference)
#include <cuda_runtime.h>

#define NN   100000
#define D    128
#define EH   600000
#define RRG  8
#define RHET 4
#define EREL 150000

// ---- scratch (device globals: no cudaMalloc allowed) ----
__device__ float g_h  [NN * D];           // 51.2 MB  layer-1 output (reused per branch)
__device__ float g_agg[NN * D];           // 51.2 MB  GCN aggregation
__device__ float g_rb [NN * RRG * D];     // 409.6 MB RGCN per-relation buckets
__device__ float g_hb [NN * RHET * D];    // 204.8 MB hetero per-relation buckets

__device__ __forceinline__ float* selbuf(int w, float* dflt) {
    switch (w) {
        case 1: return g_h;
        case 2: return g_agg;
        case 3: return g_rb;
        case 4: return g_hb;
        default: return dflt;
    }
}

// ---------------------------------------------------------------------------
__global__ void __launch_bounds__(256) zero_kernel(int which, int n4) {
    float4* p = (float4*)selbuf(which, nullptr);
    int i = blockIdx.x * blockDim.x + threadIdx.x;
    int stride = gridDim.x * blockDim.x;
    float4 z = make_float4(0.f, 0.f, 0.f, 0.f);
    for (; i < n4; i += stride) p[i] = z;
}

// One warp per edge: gather 128-float src row, vector-reduce into (dst, rel) bucket.
__global__ void __launch_bounds__(256) scatter_kernel(
        int xWhich, const float* xExt,
        const int* __restrict__ src, const int* __restrict__ dst,
        const int* __restrict__ et, int relDiv,
        int outWhich, int R, int E) {
    int gw = (blockIdx.x * blockDim.x + threadIdx.x) >> 5;
    if (gw >= E) return;
    int lane = threadIdx.x & 31;
    const float4* x = (const float4*)selbuf(xWhich, (float*)xExt);
    float4* out = (float4*)selbuf(outWhich, nullptr);
    int s = src[gw];
    int d = dst[gw];
    int r = et ? et[gw] : (relDiv ? (gw / relDiv) : 0);
    float4 v = x[s * 32 + lane];
    float4* o = out + (d * R + r) * 32 + lane;
    asm volatile("red.global.add.v4.f32 [%0], {%1,%2,%3,%4};"
                 :: "l"(o), "f"(v.x), "f"(v.y), "f"(v.z), "f"(v.w)
                 : "memory");
}

// ---------------------------------------------------------------------------
// Fused multi-chunk GEMM + bias + tanh.
//   A is [N, nChunks*128] (bucket layout), W is [nChunks,128,128] contiguous.
//   Optional self-loop term X[N,128] @ Wl (RGCN).
//   PCT=0: out = tanh(sum_ch A_ch @ W_ch (+ X@Wl) + b)            (GCN / RGCN)
//   PCT=1: out = (1/nChunks) * sum_ch tanh(A_ch @ W_ch + b_ch)    (hetero mean)
// Block = 128 threads handles 32 rows x 128 cols; thread tile = 8 rows x 4 cols.
template <int PCT>
__global__ void __launch_bounds__(128) gemm_kernel(
        int aWhich, int nChunks,
        const float* __restrict__ W,
        int xWhich, const float* xExt, const float* __restrict__ Wl,
        const float* __restrict__ b,
        float* outExt, int outWhich) {
    __shared__ float sA[32 * 128];

    const float* A = selbuf(aWhich, nullptr);
    const float* X = (Wl != nullptr) ? selbuf(xWhich, (float*)xExt) : nullptr;
    float* out = selbuf(outWhich, outExt);

    int t  = threadIdx.x;
    int c4 = t & 31;          // float4 column group
    int rg = t >> 5;          // warp id -> 8-row group
    int n0 = blockIdx.x * 32;
    int ldA = nChunks * 128;

    float fin[8][4];
    float acc[8][4];
#pragma unroll
    for (int r = 0; r < 8; r++)
#pragma unroll
        for (int j = 0; j < 4; j++) { fin[r][j] = 0.f; acc[r][j] = 0.f; }

    int totChunks = nChunks + (X ? 1 : 0);
    for (int ch = 0; ch < totChunks; ch++) {
        const float* Asrc; int ld; int kOff; const float* Wc;
        if (ch < nChunks) { Asrc = A; ld = ldA; kOff = ch * 128; Wc = W + ch * (128 * 128); }
        else              { Asrc = X; ld = 128; kOff = 0;        Wc = Wl; }

        __syncthreads();
#pragma unroll
        for (int i = 0; i < 8; i++) {
            int f   = t + i * 128;      // float4 index within 32x128 tile
            int row = f >> 5;
            int kc  = f & 31;
            float4 v = *(const float4*)(Asrc + (size_t)(n0 + row) * ld + kOff + kc * 4);
            *(float4*)(sA + row * 128 + kc * 4) = v;
        }
        __syncthreads();

        const float* sArow = sA + rg * 8 * 128;
#pragma unroll 4
        for (int k = 0; k < 128; k++) {
            float4 w4 = *(const float4*)(Wc + k * 128 + c4 * 4);
#pragma unroll
            for (int r = 0; r < 8; r++) {
                float a = sArow[r * 128 + k];
                acc[r][0] += a * w4.x;
                acc[r][1] += a * w4.y;
                acc[r][2] += a * w4.z;
                acc[r][3] += a * w4.w;
            }
        }

        if (PCT) {
            float4 b4 = *(const float4*)(b + ch * 128 + c4 * 4);
#pragma unroll
            for (int r = 0; r < 8; r++) {
                fin[r][0] += tanhf(acc[r][0] + b4.x);
                fin[r][1] += tanhf(acc[r][1] + b4.y);
                fin[r][2] += tanhf(acc[r][2] + b4.z);
                fin[r][3] += tanhf(acc[r][3] + b4.w);
                acc[r][0] = acc[r][1] = acc[r][2] = acc[r][3] = 0.f;
            }
        }
    }

    float scale = PCT ? (1.0f / (float)nChunks) : 1.0f;
    float4 b4;
    if (!PCT) b4 = *(const float4*)(b + c4 * 4);
#pragma unroll
    for (int r = 0; r < 8; r++) {
        int n = n0 + rg * 8 + r;
        float4 o;
        if (PCT) {
            o.x = fin[r][0] * scale; o.y = fin[r][1] * scale;
            o.z = fin[r][2] * scale; o.w = fin[r][3] * scale;
        } else {
            o.x = tanhf(acc[r][0] + b4.x); o.y = tanhf(acc[r][1] + b4.y);
            o.z = tanhf(acc[r][2] + b4.z); o.w = tanhf(acc[r][3] + b4.w);
        }
        *(float4*)(out + (size_t)n * 128 + c4 * 4) = o;
    }
}

// ---------------------------------------------------------------------------
extern "C" void kernel_launch(void* const* d_in, const int* in_sizes, int n_in,
                              void* d_out, int out_size) {
    const int*   gcn_src1 = (const int*)d_in[0];
    const int*   gcn_dst1 = (const int*)d_in[1];
    const int*   gcn_src2 = (const int*)d_in[2];
    const int*   gcn_dst2 = (const int*)d_in[3];
    const int*   rg_src1  = (const int*)d_in[4];
    const int*   rg_dst1  = (const int*)d_in[5];
    const int*   rg_et1   = (const int*)d_in[6];
    const int*   rg_src2  = (const int*)d_in[7];
    const int*   rg_dst2  = (const int*)d_in[8];
    const int*   rg_et2   = (const int*)d_in[9];
    const int*   het_src1 = (const int*)d_in[10];
    const int*   het_dst1 = (const int*)d_in[11];
    const int*   het_src2 = (const int*)d_in[12];
    const int*   het_dst2 = (const int*)d_in[13];
    const float* emb      = (const float*)d_in[14];
    const float* gcn_W1   = (const float*)d_in[15];
    const float* gcn_b1   = (const float*)d_in[16];
    const float* gcn_W2   = (const float*)d_in[17];
    const float* gcn_b2   = (const float*)d_in[18];
    const float* rg_W1    = (const float*)d_in[19];
    const float* rg_loop1 = (const float*)d_in[20];
    const float* rg_b1    = (const float*)d_in[21];
    const float* rg_W2    = (const float*)d_in[22];
    const float* rg_loop2 = (const float*)d_in[23];
    const float* rg_b2    = (const float*)d_in[24];
    const float* het_W1   = (const float*)d_in[25];
    const float* het_b1   = (const float*)d_in[26];
    const float* het_W2   = (const float*)d_in[27];
    const float* het_b2   = (const float*)d_in[28];

    float* out_hcf = (float*)d_out;
    float* out_hc  = out_hcf + (size_t)NN * D;
    float* out_hs  = out_hcf + (size_t)2 * NN * D;

    const int ZB = 256, ZG = 2048;
    const int sgrid = EH / 8;     // 8 edges (warps) per 256-thread block
    const int ggrid = NN / 32;    // 3125 blocks

    // ---- GCN branch ----
    zero_kernel<<<ZG, ZB>>>(2, NN * 32);
    scatter_kernel<<<sgrid, 256>>>(0, emb, gcn_src1, gcn_dst1, nullptr, 0, 2, 1, EH);
    gemm_kernel<0><<<ggrid, 128>>>(2, 1, gcn_W1, 0, nullptr, nullptr, gcn_b1, nullptr, 1);
    zero_kernel<<<ZG, ZB>>>(2, NN * 32);
    scatter_kernel<<<sgrid, 256>>>(1, nullptr, gcn_src2, gcn_dst2, nullptr, 0, 2, 1, EH);
    gemm_kernel<0><<<ggrid, 128>>>(2, 1, gcn_W2, 0, nullptr, nullptr, gcn_b2, out_hcf, 0);

    // ---- RGCN branch ----
    zero_kernel<<<ZG, ZB>>>(3, NN * RRG * 32);
    scatter_kernel<<<sgrid, 256>>>(0, emb, rg_src1, rg_dst1, rg_et1, 0, 3, RRG, EH);
    gemm_kernel<0><<<ggrid, 128>>>(3, RRG, rg_W1, 0, emb, rg_loop1, rg_b1, nullptr, 1);
    zero_kernel<<<ZG, ZB>>>(3, NN * RRG * 32);
    scatter_kernel<<<sgrid, 256>>>(1, nullptr, rg_src2, rg_dst2, rg_et2, 0, 3, RRG, EH);
    gemm_kernel<0><<<ggrid, 128>>>(3, RRG, rg_W2, 1, nullptr, rg_loop2, rg_b2, out_hc, 0);

    // ---- Hetero branch ----
    zero_kernel<<<ZG, ZB>>>(4, NN * RHET * 32);
    scatter_kernel<<<sgrid, 256>>>(0, emb, het_src1, het_dst1, nullptr, EREL, 4, RHET, EH);
    gemm_kernel<1><<<ggrid, 128>>>(4, RHET, het_W1, 0, nullptr, nullptr, het_b1, nullptr, 1);
    zero_kernel<<<ZG, ZB>>>(4, NN * RHET * 32);
    scatter_kernel<<<sgrid, 256>>>(1, nullptr, het_src2, het_dst2, nullptr, EREL, 4, RHET, EH);
    gemm_kernel<1><<<ggrid, 128>>>(4, RHET, het_W2, 0, nullptr, nullptr, het_b2, out_hs, 0);
}

// round 2
// speedup vs baseline: 1.2451x; 1.2451x over previous
#include <cuda_runtime.h>

#define NN   100000
#define D    128
#define EH   600000
#define RRG  8
#define RHET 4
#define EREL 150000

typedef unsigned long long u64;

// ---- scratch (device globals: no cudaMalloc allowed) ----
__device__ float g_h  [NN * D];           // 51.2 MB  layer-1 output (reused per branch)
__device__ float g_agg[NN * D];           // 51.2 MB  GCN aggregation
__device__ float g_rb [NN * RRG * D];     // 409.6 MB RGCN per-relation buckets
__device__ float g_hb [NN * RHET * D];    // 204.8 MB hetero per-relation buckets

__device__ __forceinline__ float* selbuf(int w, float* dflt) {
    switch (w) {
        case 1: return g_h;
        case 2: return g_agg;
        case 3: return g_rb;
        case 4: return g_hb;
        default: return dflt;
    }
}

// ---- packed f32x2 helpers (sm_100+ FFMA2 path; ptxas never emits from C++) ----
__device__ __forceinline__ u64 dup2(float a) {
    u64 r; asm("mov.b64 %0, {%1,%1};" : "=l"(r) : "f"(a)); return r;
}
__device__ __forceinline__ float2 unpk2(u64 v) {
    float2 r; asm("mov.b64 {%0,%1}, %2;" : "=f"(r.x), "=f"(r.y) : "l"(v)); return r;
}
__device__ __forceinline__ void fma2(u64& acc, u64 a, u64 b) {
    asm("fma.rn.f32x2 %0, %1, %2, %0;" : "+l"(acc) : "l"(a), "l"(b));
}

// ---------------------------------------------------------------------------
__global__ void __launch_bounds__(256) zero_kernel(int which, int n4) {
    float4* p = (float4*)selbuf(which, nullptr);
    int i = blockIdx.x * blockDim.x + threadIdx.x;
    int stride = gridDim.x * blockDim.x;
    float4 z = make_float4(0.f, 0.f, 0.f, 0.f);
    for (; i < n4; i += stride) p[i] = z;
}

// One warp per edge: gather 128-float src row, vector-reduce into (dst, rel) bucket.
__global__ void __launch_bounds__(256) scatter_kernel(
        int xWhich, const float* xExt,
        const int* __restrict__ src, const int* __restrict__ dst,
        const int* __restrict__ et, int relDiv,
        int outWhich, int R, int E) {
    int gw = (blockIdx.x * blockDim.x + threadIdx.x) >> 5;
    if (gw >= E) return;
    int lane = threadIdx.x & 31;
    const float4* x = (const float4*)selbuf(xWhich, (float*)xExt);
    float4* out = (float4*)selbuf(outWhich, nullptr);
    int s = src[gw];
    int d = dst[gw];
    int r = et ? et[gw] : (relDiv ? (gw / relDiv) : 0);
    float4 v = x[s * 32 + lane];
    float4* o = out + (d * R + r) * 32 + lane;
    asm volatile("red.global.add.v4.f32 [%0], {%1,%2,%3,%4};"
                 :: "l"(o), "f"(v.x), "f"(v.y), "f"(v.z), "f"(v.w)
                 : "memory");
}

// ---------------------------------------------------------------------------
// Fused multi-chunk GEMM + bias + tanh, FFMA2 (f32x2) inner loop.
//   A is [N, nChunks*128] (bucket layout), W is [nChunks,128,128] contiguous.
//   Optional self-loop term X[N,128] @ Wl (RGCN).
//   PCT=0: out = tanh(sum_ch A_ch @ W_ch (+ X@Wl) + b)            (GCN / RGCN)
//   PCT=1: out = (1/nChunks) * sum_ch tanh(A_ch @ W_ch + b_ch)    (hetero mean)
// Block = 128 threads handles 32 rows x 128 cols; thread tile = 8 rows x 4 cols
// (kept as 2 packed f32x2 accumulators per row).
template <int PCT>
__global__ void __launch_bounds__(128) gemm_kernel(
        int aWhich, int nChunks,
        const float* __restrict__ W,
        int xWhich, const float* xExt, const float* __restrict__ Wl,
        const float* __restrict__ b,
        float* outExt, int outWhich) {
    __shared__ float sA[32 * 128];

    const float* A = selbuf(aWhich, nullptr);
    const float* X = (Wl != nullptr) ? selbuf(xWhich, (float*)xExt) : nullptr;
    float* out = selbuf(outWhich, outExt);

    int t  = threadIdx.x;
    int c4 = t & 31;          // float4 column group
    int rg = t >> 5;          // warp id -> 8-row group
    int n0 = blockIdx.x * 32;
    int ldA = nChunks * 128;

    u64   acc[8][2];          // 8 rows x 4 cols as 2 packed f32x2 per row
    float fin[8][4];
#pragma unroll
    for (int r = 0; r < 8; r++) {
        acc[r][0] = 0ull; acc[r][1] = 0ull;
#pragma unroll
        for (int j = 0; j < 4; j++) fin[r][j] = 0.f;
    }

    int totChunks = nChunks + (X ? 1 : 0);
    for (int ch = 0; ch < totChunks; ch++) {
        const float* Asrc; int ld; int kOff; const float* Wc;
        if (ch < nChunks) { Asrc = A; ld = ldA; kOff = ch * 128; Wc = W + ch * (128 * 128); }
        else              { Asrc = X; ld = 128; kOff = 0;        Wc = Wl; }

        __syncthreads();
#pragma unroll
        for (int i = 0; i < 8; i++) {
            int f   = t + i * 128;      // float4 index within 32x128 tile
            int row = f >> 5;
            int kc  = f & 31;
            float4 v = *(const float4*)(Asrc + (size_t)(n0 + row) * ld + kOff + kc * 4);
            *(float4*)(sA + row * 128 + kc * 4) = v;
        }
        __syncthreads();

        const float* sArow = sA + rg * 8 * 128;
        // k in groups of 4: one LDS.128 per row per group, FFMA2 math.
        for (int k4 = 0; k4 < 32; k4++) {
            float4 a4[8];
#pragma unroll
            for (int r = 0; r < 8; r++)
                a4[r] = *(const float4*)(sArow + r * 128 + k4 * 4);
#pragma unroll
            for (int kk = 0; kk < 4; kk++) {
                ulonglong2 w2 = *(const ulonglong2*)(Wc + (k4 * 4 + kk) * 128 + c4 * 4);
#pragma unroll
                for (int r = 0; r < 8; r++) {
                    float a = (kk == 0) ? a4[r].x : (kk == 1) ? a4[r].y
                             : (kk == 2) ? a4[r].z : a4[r].w;
                    u64 aa = dup2(a);
                    fma2(acc[r][0], aa, w2.x);
                    fma2(acc[r][1], aa, w2.y);
                }
            }
        }

        if (PCT) {
            float4 b4 = *(const float4*)(b + ch * 128 + c4 * 4);
#pragma unroll
            for (int r = 0; r < 8; r++) {
                float2 p0 = unpk2(acc[r][0]);
                float2 p1 = unpk2(acc[r][1]);
                fin[r][0] += tanhf(p0.x + b4.x);
                fin[r][1] += tanhf(p0.y + b4.y);
                fin[r][2] += tanhf(p1.x + b4.z);
                fin[r][3] += tanhf(p1.y + b4.w);
                acc[r][0] = 0ull; acc[r][1] = 0ull;
            }
        }
    }

    float scale = PCT ? (1.0f / (float)nChunks) : 1.0f;
    float4 b4;
    if (!PCT) b4 = *(const float4*)(b + c4 * 4);
#pragma unroll
    for (int r = 0; r < 8; r++) {
        int n = n0 + rg * 8 + r;
        float4 o;
        if (PCT) {
            o.x = fin[r][0] * scale; o.y = fin[r][1] * scale;
            o.z = fin[r][2] * scale; o.w = fin[r][3] * scale;
        } else {
            float2 p0 = unpk2(acc[r][0]);
            float2 p1 = unpk2(acc[r][1]);
            o.x = tanhf(p0.x + b4.x); o.y = tanhf(p0.y + b4.y);
            o.z = tanhf(p1.x + b4.z); o.w = tanhf(p1.y + b4.w);
        }
        *(float4*)(out + (size_t)n * 128 + c4 * 4) = o;
    }
}

// ---------------------------------------------------------------------------
extern "C" void kernel_launch(void* const* d_in, const int* in_sizes, int n_in,
                              void* d_out, int out_size) {
    const int*   gcn_src1 = (const int*)d_in[0];
    const int*   gcn_dst1 = (const int*)d_in[1];
    const int*   gcn_src2 = (const int*)d_in[2];
    const int*   gcn_dst2 = (const int*)d_in[3];
    const int*   rg_src1  = (const int*)d_in[4];
    const int*   rg_dst1  = (const int*)d_in[5];
    const int*   rg_et1   = (const int*)d_in[6];
    const int*   rg_src2  = (const int*)d_in[7];
    const int*   rg_dst2  = (const int*)d_in[8];
    const int*   rg_et2   = (const int*)d_in[9];
    const int*   het_src1 = (const int*)d_in[10];
    const int*   het_dst1 = (const int*)d_in[11];
    const int*   het_src2 = (const int*)d_in[12];
    const int*   het_dst2 = (const int*)d_in[13];
    const float* emb      = (const float*)d_in[14];
    const float* gcn_W1   = (const float*)d_in[15];
    const float* gcn_b1   = (const float*)d_in[16];
    const float* gcn_W2   = (const float*)d_in[17];
    const float* gcn_b2   = (const float*)d_in[18];
    const float* rg_W1    = (const float*)d_in[19];
    const float* rg_loop1 = (const float*)d_in[20];
    const float* rg_b1    = (const float*)d_in[21];
    const float* rg_W2    = (const float*)d_in[22];
    const float* rg_loop2 = (const float*)d_in[23];
    const float* rg_b2    = (const float*)d_in[24];
    const float* het_W1   = (const float*)d_in[25];
    const float* het_b1   = (const float*)d_in[26];
    const float* het_W2   = (const float*)d_in[27];
    const float* het_b2   = (const float*)d_in[28];

    float* out_hcf = (float*)d_out;
    float* out_hc  = out_hcf + (size_t)NN * D;
    float* out_hs  = out_hcf + (size_t)2 * NN * D;

    const int ZB = 256, ZG = 2048;
    const int sgrid = EH / 8;     // 8 edges (warps) per 256-thread block
    const int ggrid = NN / 32;    // 3125 blocks

    // ---- GCN branch ----
    zero_kernel<<<ZG, ZB>>>(2, NN * 32);
    scatter_kernel<<<sgrid, 256>>>(0, emb, gcn_src1, gcn_dst1, nullptr, 0, 2, 1, EH);
    gemm_kernel<0><<<ggrid, 128>>>(2, 1, gcn_W1, 0, nullptr, nullptr, gcn_b1, nullptr, 1);
    zero_kernel<<<ZG, ZB>>>(2, NN * 32);
    scatter_kernel<<<sgrid, 256>>>(1, nullptr, gcn_src2, gcn_dst2, nullptr, 0, 2, 1, EH);
    gemm_kernel<0><<<ggrid, 128>>>(2, 1, gcn_W2, 0, nullptr, nullptr, gcn_b2, out_hcf, 0);

    // ---- RGCN branch ----
    zero_kernel<<<ZG, ZB>>>(3, NN * RRG * 32);
    scatter_kernel<<<sgrid, 256>>>(0, emb, rg_src1, rg_dst1, rg_et1, 0, 3, RRG, EH);
    gemm_kernel<0><<<ggrid, 128>>>(3, RRG, rg_W1, 0, emb, rg_loop1, rg_b1, nullptr, 1);
    zero_kernel<<<ZG, ZB>>>(3, NN * RRG * 32);
    scatter_kernel<<<sgrid, 256>>>(1, nullptr, rg_src2, rg_dst2, rg_et2, 0, 3, RRG, EH);
    gemm_kernel<0><<<ggrid, 128>>>(3, RRG, rg_W2, 1, nullptr, rg_loop2, rg_b2, out_hc, 0);

    // ---- Hetero branch ----
    zero_kernel<<<ZG, ZB>>>(4, NN * RHET * 32);
    scatter_kernel<<<sgrid, 256>>>(0, emb, het_src1, het_dst1, nullptr, EREL, 4, RHET, EH);
    gemm_kernel<1><<<ggrid, 128>>>(4, RHET, het_W1, 0, nullptr, nullptr, het_b1, nullptr, 1);
    zero_kernel<<<ZG, ZB>>>(4, NN * RHET * 32);
    scatter_kernel<<<sgrid, 256>>>(1, nullptr, het_src2, het_dst2, nullptr, EREL, 4, RHET, EH);
    gemm_kernel<1><<<ggrid, 128>>>(4, RHET, het_W2, 0, nullptr, nullptr, het_b2, out_hs, 0);
}